// round 15
// baseline (speedup 1.0000x reference)
#include <cuda_runtime.h>
#include <cuda_fp16.h>
#include <math.h>
#include <stdint.h>

// Problem constants
#define D_MODEL 2048
#define SEQ     2048
#define BATCH   2
#define NHEAD   16
#define KVHEAD  4
#define HDIM    128
#define FF      5632
#define MTOT    (BATCH * SEQ)      // 4096
#define KD      (KVHEAD * HDIM)    // 512
#define QKV_N   3072
#define VOFF    2560

// ---------------------------------------------------------------------------
// Scratch (no cudaMalloc allowed)
// ---------------------------------------------------------------------------
__device__ __half g_h  [MTOT * (size_t)D_MODEL];   // rms1 out / attn out (half, pair-perm)
__device__ __half g_h2 [MTOT * (size_t)D_MODEL];   // rms2 out (half, pair-perm)
__device__ __half g_qkv[MTOT * (size_t)QKV_N];     // q|k plain half (v cols unused)
__device__ __half g_vT [(size_t)BATCH * KVHEAD * HDIM * SEQ];  // V transposed [b][g][d][seq]
__device__ __half g_act[MTOT * (size_t)FF];        // swiglu (half, pair-perm)
// fp16 pair-permuted weights
__device__ __half w_qkvh[(size_t)QKV_N * D_MODEL];
__device__ __half w_oh  [(size_t)D_MODEL * D_MODEL];
__device__ __half w_gh  [(size_t)FF * D_MODEL];
__device__ __half w_uh  [(size_t)FF * D_MODEL];
__device__ __half w_dh  [(size_t)D_MODEL * FF];
__device__ float  b_qkv [QKV_N];

// Pair-permutation on 16-element K-groups (GEMM operands only)
__device__ __forceinline__ int ppos(int col) {
    const int j = (col >> 1) & 7;
    return (col & ~15) + 2 * ((j & 3) * 2 + (j >> 2));
}

#define MMA_F16(d, a, b)                                                    \
    asm volatile(                                                           \
        "mma.sync.aligned.m16n8k16.row.col.f32.f16.f16.f32 "                \
        "{%0,%1,%2,%3}, {%4,%5,%6,%7}, {%8,%9}, {%0,%1,%2,%3};"             \
        : "+f"(d[0]), "+f"(d[1]), "+f"(d[2]), "+f"(d[3])                    \
        : "r"(a[0]), "r"(a[1]), "r"(a[2]), "r"(a[3]), "r"(b[0]), "r"(b[1]))

__device__ __forceinline__ void cp_async16(void* dst, const void* src) {
    uint32_t s = (uint32_t)__cvta_generic_to_shared(dst);
    asm volatile("cp.async.cg.shared.global [%0], [%1], 16;\n" :: "r"(s), "l"(src));
}
__device__ __forceinline__ void cp_commit() {
    asm volatile("cp.async.commit_group;\n");
}
template<int N> __device__ __forceinline__ void cp_wait() {
    asm volatile("cp.async.wait_group %0;\n" :: "n"(N));
}

// ---------------------------------------------------------------------------
// cvt: fp32 weights -> fp16 pair-permuted; biases -> fp32 concat copy.
// ---------------------------------------------------------------------------
#define NSEG 10
struct CvtArgs {
    const float* s[NSEG];
    void* d[NSEG];
    int end[NSEG];
    int perm;
};

__global__ void __launch_bounds__(256) cvt_all_kernel(CvtArgs a, int totalg)
{
    const int i = blockIdx.x * 256 + threadIdx.x;
    if (i >= totalg) return;
    int j = 0;
    #pragma unroll
    for (int t = 0; t < NSEG - 1; ++t)
        if (i >= a.end[t]) j = t + 1;
    const int gi = i - (j ? a.end[j - 1] : 0);
    const float4* s = (const float4*)a.s[j] + gi * 4;
    float4 f0 = s[0], f1 = s[1], f2 = s[2], f3 = s[3];
    if ((a.perm >> j) & 1) {
        float n[16] = { f0.x,f0.y,f0.z,f0.w, f1.x,f1.y,f1.z,f1.w,
                        f2.x,f2.y,f2.z,f2.w, f3.x,f3.y,f3.z,f3.w };
        uint32_t w[8];
        #pragma unroll
        for (int p = 0; p < 8; ++p) {
            const int pp = (p & 3) * 2 + (p >> 2);
            __half2 h = __floats2half2_rn(n[2 * p], n[2 * p + 1]);
            w[pp] = *(uint32_t*)&h;
        }
        uint4* d = (uint4*)a.d[j] + gi * 2;
        uint4 o0; o0.x = w[0]; o0.y = w[1]; o0.z = w[2]; o0.w = w[3];
        uint4 o1; o1.x = w[4]; o1.y = w[5]; o1.z = w[6]; o1.w = w[7];
        d[0] = o0; d[1] = o1;
    } else {
        float4* d = (float4*)a.d[j] + gi * 4;
        d[0] = f0; d[1] = f1; d[2] = f2; d[3] = f3;
    }
}

// ---------------------------------------------------------------------------
// RMSNorm: fp32 in -> half pair-permuted out.
// ---------------------------------------------------------------------------
__global__ void __launch_bounds__(128) rmsnorm_kernel(
    const float* __restrict__ x, const float* __restrict__ w,
    __half* __restrict__ o)
{
    const int row = blockIdx.x;
    const float* xr = x + (size_t)row * D_MODEL;
    const int t = threadIdx.x;
    const int c0 = 16 * t;

    float4 f0 = *(const float4*)(xr + c0);
    float4 f1 = *(const float4*)(xr + c0 + 4);
    float4 f2 = *(const float4*)(xr + c0 + 8);
    float4 f3 = *(const float4*)(xr + c0 + 12);
    float n[16] = { f0.x,f0.y,f0.z,f0.w, f1.x,f1.y,f1.z,f1.w,
                    f2.x,f2.y,f2.z,f2.w, f3.x,f3.y,f3.z,f3.w };
    float ss = 0.f;
    #pragma unroll
    for (int i = 0; i < 16; ++i) ss += n[i] * n[i];
    #pragma unroll
    for (int off = 16; off; off >>= 1)
        ss += __shfl_xor_sync(0xffffffffu, ss, off);
    __shared__ float warp_s[4];
    if ((t & 31) == 0) warp_s[t >> 5] = ss;
    __syncthreads();
    float tot = warp_s[0] + warp_s[1] + warp_s[2] + warp_s[3];
    const float inv = rsqrtf(tot * (1.0f / D_MODEL) + 1e-6f);

    float4 w0 = *(const float4*)(w + c0);
    float4 w1 = *(const float4*)(w + c0 + 4);
    float4 w2 = *(const float4*)(w + c0 + 8);
    float4 w3 = *(const float4*)(w + c0 + 12);
    float wv[16] = { w0.x,w0.y,w0.z,w0.w, w1.x,w1.y,w1.z,w1.w,
                     w2.x,w2.y,w2.z,w2.w, w3.x,w3.y,w3.z,w3.w };
    uint32_t wd[8];
    #pragma unroll
    for (int p = 0; p < 8; ++p) {
        const int pp = (p & 3) * 2 + (p >> 2);
        __half2 h = __floats2half2_rn(n[2 * p] * inv * wv[2 * p],
                                      n[2 * p + 1] * inv * wv[2 * p + 1]);
        wd[pp] = *(uint32_t*)&h;
    }
    uint4* d = (uint4*)(o + (size_t)row * D_MODEL + c0);
    uint4 o0; o0.x = wd[0]; o0.y = wd[1]; o0.z = wd[2]; o0.w = wd[3];
    uint4 o1; o1.x = wd[4]; o1.y = wd[5]; o1.z = wd[6]; o1.w = wd[7];
    d[0] = o0; d[1] = o1;
}

// ---------------------------------------------------------------------------
// FP16 GEMM: 128x128 tile, 8 warps 64x32, BK=32, 3-stage cp.async ring,
// loads issued BEFORE compute each iteration. Stride 24 words (conflict-free
// per 16-lane LDS.64 phase). 2 CTAs/SM.
//   EPI 0: +bias[col]  EPI 1: +aux fp32 matrix
//   OUT 0: fp32 plain  OUT 1: half pair-perm  OUT 2: half plain
//   OUT 3: qkv special — q/k plain half to Cv, v transposed to Cv2
// ---------------------------------------------------------------------------
#define GST2 24                               // words per smem row (32 halves + pad)
#define STG2_W (256 * GST2)                   // A(128)+B(128) rows: 6144 words
#define GEMM_SMEM (3 * STG2_W * 4)            // 73728 bytes

template<int EPI, int OUT>
__global__ void __launch_bounds__(256, 2) gemm_f16(
    const __half* __restrict__ A, const __half* __restrict__ W,
    const void* aux, void* __restrict__ Cv, void* __restrict__ Cv2,
    int M, int N, int K)
{
    extern __shared__ uint32_t smw[];
    const int tid  = threadIdx.x;
    const int warp = tid >> 5;
    const int lane = tid & 31;
    const int bm = blockIdx.y * 128;
    const int bn = blockIdx.x * 128;
    const int m_w = (warp >> 2) * 64;
    const int n_w = (warp & 3) * 32;
    const int lr4 = lane >> 2;
    const int lk  = lane & 3;

    const __half* Ab = A + (size_t)bm * K;
    const __half* Wb = W + (size_t)bn * K;

    float acc[4][4][4];
    #pragma unroll
    for (int mt = 0; mt < 4; ++mt)
        #pragma unroll
        for (int nt = 0; nt < 4; ++nt)
            #pragma unroll
            for (int r = 0; r < 4; ++r) acc[mt][nt][r] = 0.f;

    const int nk = K / 32;

    auto load_stage = [&](int st, int k0) {   // k0 in halves
        uint32_t* Aw = smw + st * STG2_W;
        uint32_t* Bw = Aw + 128 * GST2;
        #pragma unroll
        for (int i = 0; i < 2; ++i) {
            const int idx = tid + i * 256;
            const int row = idx >> 2;
            const int ch  = idx & 3;
            cp_async16(&Aw[row * GST2 + ch * 4], Ab + (size_t)row * K + k0 + ch * 8);
            cp_async16(&Bw[row * GST2 + ch * 4], Wb + (size_t)row * K + k0 + ch * 8);
        }
    };

    load_stage(0, 0);   cp_commit();
    load_stage(1, 32);  cp_commit();

    for (int kt = 0; kt < nk; ++kt) {
        cp_wait<1>();
        __syncthreads();
        if (kt + 2 < nk) load_stage((kt + 2) % 3, (kt + 2) * 32);
        cp_commit();

        const uint32_t* As = smw + (kt % 3) * STG2_W;
        const uint32_t* Bs = As + 128 * GST2;
        #pragma unroll
        for (int kk = 0; kk < 2; ++kk) {
            const int k0 = kk * 8;
            uint32_t afr[4][4], bfr[4][2];
            #pragma unroll
            for (int mt = 0; mt < 4; ++mt) {
                const int r = m_w + mt * 16 + lr4;
                const uint2 lo = *(const uint2*)&As[r * GST2 + k0 + 2 * lk];
                const uint2 hi = *(const uint2*)&As[(r + 8) * GST2 + k0 + 2 * lk];
                afr[mt][0] = lo.x; afr[mt][2] = lo.y;
                afr[mt][1] = hi.x; afr[mt][3] = hi.y;
            }
            #pragma unroll
            for (int nt = 0; nt < 4; ++nt) {
                const int rn = n_w + nt * 8 + lr4;
                const uint2 bb = *(const uint2*)&Bs[rn * GST2 + k0 + 2 * lk];
                bfr[nt][0] = bb.x; bfr[nt][1] = bb.y;
            }
            #pragma unroll
            for (int mt = 0; mt < 4; ++mt)
                #pragma unroll
                for (int nt = 0; nt < 4; ++nt)
                    MMA_F16(acc[mt][nt], afr[mt], bfr[nt]);
        }
    }

    // ---- epilogue ----
    #pragma unroll
    for (int mt = 0; mt < 4; ++mt) {
        #pragma unroll
        for (int half = 0; half < 2; ++half) {
            const int row = bm + m_w + mt * 16 + lr4 + half * 8;
            const size_t base = (size_t)row * N;
            #pragma unroll
            for (int nt = 0; nt < 4; ++nt) {
                const int col = bn + n_w + nt * 8 + 2 * lk;
                float v0 = acc[mt][nt][half * 2 + 0];
                float v1 = acc[mt][nt][half * 2 + 1];
                if (EPI == 0) {
                    if (aux) {
                        const float* bz = (const float*)aux;
                        v0 += bz[col]; v1 += bz[col + 1];
                    }
                } else if (EPI == 1) {
                    const float* r = (const float*)aux;
                    v0 += r[base + col]; v1 += r[base + col + 1];
                }
                if (OUT == 0) {
                    float2 r; r.x = v0; r.y = v1;
                    *(float2*)((float*)Cv + base + col) = r;
                } else if (OUT == 1) {
                    *(__half2*)((__half*)Cv + base + ppos(col)) = __floats2half2_rn(v0, v1);
                } else if (OUT == 2) {
                    *(__half2*)((__half*)Cv + base + col) = __floats2half2_rn(v0, v1);
                } else {
                    if (col < VOFF) {
                        *(__half2*)((__half*)Cv + base + col) = __floats2half2_rn(v0, v1);
                    } else {
                        const int c = col - VOFF;
                        const int gidx = c >> 7, d = c & 127;
                        const int bb = row >> 11, sp = row & (SEQ - 1);
                        __half* vt = (__half*)Cv2 +
                            ((size_t)(bb * KVHEAD + gidx) * HDIM + d) * SEQ + sp;
                        vt[0]   = __float2half_rn(v0);
                        vt[SEQ] = __float2half_rn(v1);
                    }
                }
            }
        }
    }
}

// ---------------------------------------------------------------------------
// Fused gate+up GEMM: BK=32, 3-stage ring, loads-before-compute.
// A 128 rows + G 64 + U 64 = 256 rows/stage (same stage size as gemm_f16).
// ---------------------------------------------------------------------------
__global__ void __launch_bounds__(256, 2) gemm_gateup(
    const __half* __restrict__ A, const __half* __restrict__ Wg,
    const __half* __restrict__ Wu, __half* __restrict__ act,
    int M, int N, int K)
{
    extern __shared__ uint32_t smw[];
    const int tid  = threadIdx.x;
    const int warp = tid >> 5;
    const int lane = tid & 31;
    const int bm = blockIdx.y * 128;
    const int bn = blockIdx.x * 64;
    const int m_w = (warp >> 2) * 64;
    const int n_w = (warp & 3) * 16;
    const int lr4 = lane >> 2;
    const int lk  = lane & 3;

    const __half* Ab = A  + (size_t)bm * K;
    const __half* Gb = Wg + (size_t)bn * K;
    const __half* Ub = Wu + (size_t)bn * K;

    float ag[4][2][4], au[4][2][4];
    #pragma unroll
    for (int mt = 0; mt < 4; ++mt)
        #pragma unroll
        for (int nt = 0; nt < 2; ++nt)
            #pragma unroll
            for (int r = 0; r < 4; ++r) { ag[mt][nt][r] = 0.f; au[mt][nt][r] = 0.f; }

    const int nk = K / 32;

    auto load_stage = [&](int st, int k0) {
        uint32_t* Aw = smw + st * STG2_W;
        uint32_t* Gw = Aw + 128 * GST2;
        uint32_t* Uw = Aw + 192 * GST2;
        #pragma unroll
        for (int i = 0; i < 2; ++i) {
            const int idx = tid + i * 256;
            const int row = idx >> 2;
            const int ch  = idx & 3;
            cp_async16(&Aw[row * GST2 + ch * 4], Ab + (size_t)row * K + k0 + ch * 8);
        }
        {
            const int idx = tid;                 // 256 = 64 rows x 4 chunks
            const int row = idx >> 2;
            const int ch  = idx & 3;
            cp_async16(&Gw[row * GST2 + ch * 4], Gb + (size_t)row * K + k0 + ch * 8);
            cp_async16(&Uw[row * GST2 + ch * 4], Ub + (size_t)row * K + k0 + ch * 8);
        }
    };

    load_stage(0, 0);   cp_commit();
    load_stage(1, 32);  cp_commit();

    for (int kt = 0; kt < nk; ++kt) {
        cp_wait<1>();
        __syncthreads();
        if (kt + 2 < nk) load_stage((kt + 2) % 3, (kt + 2) * 32);
        cp_commit();

        const uint32_t* As = smw + (kt % 3) * STG2_W;
        const uint32_t* Gs = As + 128 * GST2;
        const uint32_t* Us = As + 192 * GST2;
        #pragma unroll
        for (int kk = 0; kk < 2; ++kk) {
            const int k0 = kk * 8;
            uint32_t afr[4][4], gfr[2][2], ufr[2][2];
            #pragma unroll
            for (int mt = 0; mt < 4; ++mt) {
                const int r = m_w + mt * 16 + lr4;
                const uint2 lo = *(const uint2*)&As[r * GST2 + k0 + 2 * lk];
                const uint2 hi = *(const uint2*)&As[(r + 8) * GST2 + k0 + 2 * lk];
                afr[mt][0] = lo.x; afr[mt][2] = lo.y;
                afr[mt][1] = hi.x; afr[mt][3] = hi.y;
            }
            #pragma unroll
            for (int nt = 0; nt < 2; ++nt) {
                const int rn = n_w + nt * 8 + lr4;
                const uint2 gg = *(const uint2*)&Gs[rn * GST2 + k0 + 2 * lk];
                gfr[nt][0] = gg.x; gfr[nt][1] = gg.y;
                const uint2 uu = *(const uint2*)&Us[rn * GST2 + k0 + 2 * lk];
                ufr[nt][0] = uu.x; ufr[nt][1] = uu.y;
            }
            #pragma unroll
            for (int mt = 0; mt < 4; ++mt)
                #pragma unroll
                for (int nt = 0; nt < 2; ++nt) {
                    MMA_F16(ag[mt][nt], afr[mt], gfr[nt]);
                    MMA_F16(au[mt][nt], afr[mt], ufr[nt]);
                }
        }
    }

    // ---- epilogue: act = silu(g) * u, half pair-perm ----
    #pragma unroll
    for (int mt = 0; mt < 4; ++mt) {
        #pragma unroll
        for (int half = 0; half < 2; ++half) {
            const int row = bm + m_w + mt * 16 + lr4 + half * 8;
            const size_t base = (size_t)row * N;
            #pragma unroll
            for (int nt = 0; nt < 2; ++nt) {
                const int col = bn + n_w + nt * 8 + 2 * lk;
                const float ga = ag[mt][nt][half * 2 + 0];
                const float gb = ag[mt][nt][half * 2 + 1];
                const float v0 = au[mt][nt][half * 2 + 0] * ga / (1.0f + __expf(-ga));
                const float v1 = au[mt][nt][half * 2 + 1] * gb / (1.0f + __expf(-gb));
                *(__half2*)(act + base + ppos(col)) = __floats2half2_rn(v0, v1);
            }
        }
    }
}

// ---------------------------------------------------------------------------
// Flash attention: fp16 MMA, FKT=128 (mask only on final diagonal tile),
// P in registers, V pre-transposed.
// ---------------------------------------------------------------------------
#define FQT 128
#define FKT 128
#define KSTH 136                       // halves (68 words/row, === 4 mod 32)
#define VSTH 136
#define KV_STAGE_H (FKT * KSTH + HDIM * VSTH)            // 34816 halves
#define FLASH_SMEM (2 * KV_STAGE_H * 2)                  // 139264 bytes

__global__ void __launch_bounds__(256) flash_tc_kernel(
    const __half* __restrict__ qkv, const __half* __restrict__ vT,
    __half* __restrict__ Ob)
{
    extern __shared__ __half fsh[];
    __half* S0 = fsh;
    __half* S1 = fsh + KV_STAGE_H;

    const int bx   = (SEQ / FQT - 1) - blockIdx.x;   // heavy tiles first
    const int hh   = blockIdx.y;
    const int b    = blockIdx.z;
    const int g    = hh & (KVHEAD - 1);
    const int tid  = threadIdx.x;
    const int warp = tid >> 5;
    const int lane = tid & 31;
    const int lr   = lane >> 2;
    const int lq   = lane & 3;
    const int mb   = warp * 16;
    const int qbase = bx * FQT;
    const float scale = 0.08838834764831845f;

    // ---- stage Q into S0, extract fp16 fragments ----
    const __half* qp = qkv + ((size_t)(b * SEQ + qbase)) * QKV_N + hh * HDIM;
    #pragma unroll
    for (int it = 0; it < 8; ++it) {
        const int idx = tid + it * 256;
        const int row = idx >> 4;
        const int ch  = idx & 15;
        *(uint4*)&S0[row * KSTH + ch * 8] =
            *(const uint4*)(qp + (size_t)row * QKV_N + ch * 8);
    }
    __syncthreads();
    uint32_t qf[8][4];
    #pragma unroll
    for (int kk = 0; kk < 8; ++kk) {
        const int k0 = kk * 16 + 2 * lq;
        qf[kk][0] = *(const uint32_t*)&S0[(mb + lr)     * KSTH + k0];
        qf[kk][1] = *(const uint32_t*)&S0[(mb + lr + 8) * KSTH + k0];
        qf[kk][2] = *(const uint32_t*)&S0[(mb + lr)     * KSTH + k0 + 8];
        qf[kk][3] = *(const uint32_t*)&S0[(mb + lr + 8) * KSTH + k0 + 8];
    }
    __syncthreads();

    const int nkt = bx + 1;

    auto load_kv = [&](__half* St, int ktb) {
        __half* Kd = St;
        __half* Vd = St + FKT * KSTH;
        const __half* kp = qkv + ((size_t)(b * SEQ + ktb)) * QKV_N + D_MODEL + g * HDIM;
        const __half* vp = vT + ((size_t)(b * KVHEAD + g) * HDIM) * SEQ + ktb;
        #pragma unroll
        for (int it = 0; it < 8; ++it) {
            const int idx = tid + it * 256;
            const int row = idx >> 4, ch = idx & 15;
            cp_async16(&Kd[row * KSTH + ch * 8], kp + (size_t)row * QKV_N + ch * 8);
            cp_async16(&Vd[row * VSTH + ch * 8], vp + (size_t)row * SEQ + ch * 8);
        }
    };

    load_kv(S0, 0);
    cp_commit();
    if (nkt > 1) load_kv(S1, FKT);
    cp_commit();

    float o[16][4];
    #pragma unroll
    for (int nt = 0; nt < 16; ++nt)
        o[nt][0] = o[nt][1] = o[nt][2] = o[nt][3] = 0.f;
    float m0 = -1e30f, m1 = -1e30f, l0 = 0.f, l1 = 0.f;
    const int r0g = qbase + mb + lr;
    const int r1g = r0g + 8;

    for (int kt = 0; kt < nkt; ++kt) {
        cp_wait<1>();
        __syncthreads();
        const __half* St = (kt & 1) ? S1 : S0;
        const __half* Ks = St;
        const __half* Vs = St + FKT * KSTH;
        const int ktb = kt * FKT;

        // ---- S = Q K^T (16 x 128 per warp), fp16 MMA ----
        float s[16][4];
        #pragma unroll
        for (int nt = 0; nt < 16; ++nt)
            s[nt][0] = s[nt][1] = s[nt][2] = s[nt][3] = 0.f;
        #pragma unroll
        for (int kk = 0; kk < 8; ++kk) {
            const int k0 = kk * 16 + 2 * lq;
            #pragma unroll
            for (int nt = 0; nt < 16; ++nt) {
                uint32_t bfr[2];
                bfr[0] = *(const uint32_t*)&Ks[(nt * 8 + lr) * KSTH + k0];
                bfr[1] = *(const uint32_t*)&Ks[(nt * 8 + lr) * KSTH + k0 + 8];
                MMA_F16(s[nt], qf[kk], bfr);
            }
        }

        // ---- scale (+ causal mask on last tile only) + max ----
        float mx0 = -1e30f, mx1 = -1e30f;
        if (kt == nkt - 1) {
            #pragma unroll
            for (int nt = 0; nt < 16; ++nt) {
                const int c = ktb + nt * 8 + 2 * lq;
                s[nt][0] = (c     <= r0g) ? s[nt][0] * scale : -1e30f;
                s[nt][1] = (c + 1 <= r0g) ? s[nt][1] * scale : -1e30f;
                s[nt][2] = (c     <= r1g) ? s[nt][2] * scale : -1e30f;
                s[nt][3] = (c + 1 <= r1g) ? s[nt][3] * scale : -1e30f;
                mx0 = fmaxf(mx0, fmaxf(s[nt][0], s[nt][1]));
                mx1 = fmaxf(mx1, fmaxf(s[nt][2], s[nt][3]));
            }
        } else {
            #pragma unroll
            for (int nt = 0; nt < 16; ++nt) {
                s[nt][0] *= scale; s[nt][1] *= scale;
                s[nt][2] *= scale; s[nt][3] *= scale;
                mx0 = fmaxf(mx0, fmaxf(s[nt][0], s[nt][1]));
                mx1 = fmaxf(mx1, fmaxf(s[nt][2], s[nt][3]));
            }
        }
        mx0 = fmaxf(mx0, __shfl_xor_sync(0xffffffffu, mx0, 1));
        mx0 = fmaxf(mx0, __shfl_xor_sync(0xffffffffu, mx0, 2));
        mx1 = fmaxf(mx1, __shfl_xor_sync(0xffffffffu, mx1, 1));
        mx1 = fmaxf(mx1, __shfl_xor_sync(0xffffffffu, mx1, 2));
        const float mn0 = fmaxf(m0, mx0), mn1 = fmaxf(m1, mx1);
        const float al0 = __expf(m0 - mn0), al1 = __expf(m1 - mn1);
        m0 = mn0; m1 = mn1;

        // ---- exp -> P as half2 A-fragments in registers ----
        uint32_t ph[16][2];
        float ps0 = 0.f, ps1 = 0.f;
        #pragma unroll
        for (int nt = 0; nt < 16; ++nt) {
            const float p0 = __expf(s[nt][0] - mn0);
            const float p1 = __expf(s[nt][1] - mn0);
            const float p2 = __expf(s[nt][2] - mn1);
            const float p3 = __expf(s[nt][3] - mn1);
            ps0 += p0 + p1; ps1 += p2 + p3;
            __half2 h0 = __floats2half2_rn(p0, p1);
            __half2 h1 = __floats2half2_rn(p2, p3);
            ph[nt][0] = *(uint32_t*)&h0;
            ph[nt][1] = *(uint32_t*)&h1;
        }
        ps0 += __shfl_xor_sync(0xffffffffu, ps0, 1);
        ps0 += __shfl_xor_sync(0xffffffffu, ps0, 2);
        ps1 += __shfl_xor_sync(0xffffffffu, ps1, 1);
        ps1 += __shfl_xor_sync(0xffffffffu, ps1, 2);
        l0 = l0 * al0 + ps0;
        l1 = l1 * al1 + ps1;

        #pragma unroll
        for (int nt = 0; nt < 16; ++nt) {
            o[nt][0] *= al0; o[nt][1] *= al0;
            o[nt][2] *= al1; o[nt][3] *= al1;
        }

        // ---- O += P V (K=128 -> 8 k16 chunks), P from registers ----
        #pragma unroll
        for (int kk = 0; kk < 8; ++kk) {
            const int k0 = kk * 16 + 2 * lq;
            uint32_t a[4];
            a[0] = ph[2 * kk][0];
            a[1] = ph[2 * kk][1];
            a[2] = ph[2 * kk + 1][0];
            a[3] = ph[2 * kk + 1][1];
            #pragma unroll
            for (int nt = 0; nt < 16; ++nt) {
                uint32_t bfr[2];
                bfr[0] = *(const uint32_t*)&Vs[(nt * 8 + lr) * VSTH + k0];
                bfr[1] = *(const uint32_t*)&Vs[(nt * 8 + lr) * VSTH + k0 + 8];
                MMA_F16(o[nt], a, bfr);
            }
        }
        __syncthreads();

        const int nx = kt + 2;
        if (nx < nkt) load_kv((nx & 1) ? S1 : S0, nx * FKT);
        cp_commit();
    }

    // write O: half pair-perm (feeds o-proj GEMM)
    const float i0 = 1.0f / l0, i1 = 1.0f / l1;
    __half* op = Ob + ((size_t)(b * SEQ + qbase + mb)) * D_MODEL;
    #pragma unroll
    for (int nt = 0; nt < 16; ++nt) {
        const int label = hh * HDIM + nt * 8 + 2 * lq;
        const int pos = ppos(label);
        *(__half2*)(op + (size_t)lr * D_MODEL + pos) =
            __floats2half2_rn(o[nt][0] * i0, o[nt][1] * i0);
        *(__half2*)(op + (size_t)(lr + 8) * D_MODEL + pos) =
            __floats2half2_rn(o[nt][2] * i1, o[nt][3] * i1);
    }
}

// ---------------------------------------------------------------------------
// Launch sequence
// ---------------------------------------------------------------------------
extern "C" void kernel_launch(void* const* d_in, const int* in_sizes, int n_in,
                              void* d_out, int out_size)
{
    const float* x      = (const float*)d_in[0];
    const float* ln1_w  = (const float*)d_in[1];
    const float* q_w    = (const float*)d_in[2];
    const float* q_b    = (const float*)d_in[3];
    const float* k_w    = (const float*)d_in[4];
    const float* k_b    = (const float*)d_in[5];
    const float* v_w    = (const float*)d_in[6];
    const float* v_b    = (const float*)d_in[7];
    const float* o_w    = (const float*)d_in[8];
    const float* ln2_w  = (const float*)d_in[9];
    const float* gate_w = (const float*)d_in[10];
    const float* up_w   = (const float*)d_in[11];
    const float* down_w = (const float*)d_in[12];
    float* out = (float*)d_out;

    __half *h, *h2, *act, *qkv, *vT;
    float *bq;
    __half *wqkv, *wo, *wg, *wu, *wd;
    cudaGetSymbolAddress((void**)&h,    g_h);
    cudaGetSymbolAddress((void**)&h2,   g_h2);
    cudaGetSymbolAddress((void**)&qkv,  g_qkv);
    cudaGetSymbolAddress((void**)&vT,   g_vT);
    cudaGetSymbolAddress((void**)&act,  g_act);
    cudaGetSymbolAddress((void**)&wqkv, w_qkvh);
    cudaGetSymbolAddress((void**)&wo,   w_oh);
    cudaGetSymbolAddress((void**)&wg,   w_gh);
    cudaGetSymbolAddress((void**)&wu,   w_uh);
    cudaGetSymbolAddress((void**)&wd,   w_dh);
    cudaGetSymbolAddress((void**)&bq,   b_qkv);

    cudaFuncSetAttribute(gemm_f16<0,3>, cudaFuncAttributeMaxDynamicSharedMemorySize, GEMM_SMEM);
    cudaFuncSetAttribute(gemm_f16<1,0>, cudaFuncAttributeMaxDynamicSharedMemorySize, GEMM_SMEM);
    cudaFuncSetAttribute(gemm_gateup,   cudaFuncAttributeMaxDynamicSharedMemorySize, GEMM_SMEM);
    cudaFuncSetAttribute(flash_tc_kernel, cudaFuncAttributeMaxDynamicSharedMemorySize, FLASH_SMEM);

    // 0. convert weights (pair-perm fp16) + concat biases
    {
        CvtArgs a;
        const float* srcs[NSEG] = { q_w, k_w, v_w, o_w, gate_w, up_w, down_w,
                                    q_b, k_b, v_b };
        void* dsts[NSEG] = { (void*)wqkv,
                             (void*)(wqkv + (size_t)D_MODEL * D_MODEL),
                             (void*)(wqkv + (size_t)VOFF * D_MODEL),
                             (void*)wo, (void*)wg, (void*)wu, (void*)wd,
                             (void*)bq, (void*)(bq + D_MODEL), (void*)(bq + VOFF) };
        const long long n[NSEG] = {
            (long long)D_MODEL*D_MODEL, (long long)KD*D_MODEL, (long long)KD*D_MODEL,
            (long long)D_MODEL*D_MODEL, (long long)FF*D_MODEL, (long long)FF*D_MODEL,
            (long long)D_MODEL*FF, D_MODEL, KD, KD };
        int accg = 0;
        for (int i = 0; i < NSEG; ++i) {
            a.s[i] = srcs[i]; a.d[i] = dsts[i];
            accg += (int)(n[i] / 16); a.end[i] = accg;
        }
        a.perm = 0x7F;
        cvt_all_kernel<<<(accg + 255) / 256, 256>>>(a, accg);
    }

    // 1. h = rmsnorm(x, ln1)  [half, perm]
    rmsnorm_kernel<<<MTOT, 128>>>(x, ln1_w, h);

    // 2. fused qkv projection: q/k plain half, v transposed
    gemm_f16<0,3><<<dim3(QKV_N/128, MTOT/128), 256, GEMM_SMEM>>>(
        h, wqkv, bq, qkv, vT, MTOT, QKV_N, D_MODEL);

    // 3. flash attention (fp16, FKT=128) -> g_h
    flash_tc_kernel<<<dim3(SEQ/FQT, NHEAD, BATCH), 256, FLASH_SMEM>>>(qkv, vT, h);

    // 4. x1 = x + attn @ o_w^T -> d_out
    gemm_f16<1,0><<<dim3(D_MODEL/128, MTOT/128), 256, GEMM_SMEM>>>(
        h, wo, x, out, nullptr, MTOT, D_MODEL, D_MODEL);

    // 5. h2 = rmsnorm(x1, ln2)  [half, perm]
    rmsnorm_kernel<<<MTOT, 128>>>(out, ln2_w, h2);

    // 6. act = silu(h2 @ gate_w^T) * (h2 @ up_w^T)  [fused]
    gemm_gateup<<<dim3(FF/64, MTOT/128), 256, GEMM_SMEM>>>(
        h2, wg, wu, act, MTOT, FF, D_MODEL);

    // 7. out = x1 + act @ down_w^T -> d_out
    gemm_f16<1,0><<<dim3(D_MODEL/128, MTOT/128), 256, GEMM_SMEM>>>(
        act, wd, out, out, nullptr, MTOT, D_MODEL, FF);
}

// round 16
// speedup vs baseline: 1.0620x; 1.0620x over previous
#include <cuda_runtime.h>
#include <cuda_fp16.h>
#include <math.h>
#include <stdint.h>

// Problem constants
#define D_MODEL 2048
#define SEQ     2048
#define BATCH   2
#define NHEAD   16
#define KVHEAD  4
#define HDIM    128
#define FF      5632
#define MTOT    (BATCH * SEQ)      // 4096
#define KD      (KVHEAD * HDIM)    // 512
#define QKV_N   3072
#define VOFF    2560

// ---------------------------------------------------------------------------
// Scratch (no cudaMalloc allowed)
// ---------------------------------------------------------------------------
__device__ __half g_h  [MTOT * (size_t)D_MODEL];   // rms1 out / attn out (half, pair-perm)
__device__ __half g_h2 [MTOT * (size_t)D_MODEL];   // rms2 out (half, pair-perm)
__device__ __half g_qkv[MTOT * (size_t)QKV_N];     // q|k plain half (v cols unused)
__device__ __half g_vT [(size_t)BATCH * KVHEAD * HDIM * SEQ];  // V transposed [b][g][d][seq]
__device__ __half g_act[MTOT * (size_t)FF];        // swiglu (half, pair-perm)
// fp16 pair-permuted weights
__device__ __half w_qkvh[(size_t)QKV_N * D_MODEL];
__device__ __half w_oh  [(size_t)D_MODEL * D_MODEL];
__device__ __half w_gh  [(size_t)FF * D_MODEL];
__device__ __half w_uh  [(size_t)FF * D_MODEL];
__device__ __half w_dh  [(size_t)D_MODEL * FF];
__device__ float  b_qkv [QKV_N];

// Pair-permutation on 16-element K-groups (GEMM operands only)
__device__ __forceinline__ int ppos(int col) {
    const int j = (col >> 1) & 7;
    return (col & ~15) + 2 * ((j & 3) * 2 + (j >> 2));
}

#define MMA_F16(d, a, b)                                                    \
    asm volatile(                                                           \
        "mma.sync.aligned.m16n8k16.row.col.f32.f16.f16.f32 "                \
        "{%0,%1,%2,%3}, {%4,%5,%6,%7}, {%8,%9}, {%0,%1,%2,%3};"             \
        : "+f"(d[0]), "+f"(d[1]), "+f"(d[2]), "+f"(d[3])                    \
        : "r"(a[0]), "r"(a[1]), "r"(a[2]), "r"(a[3]), "r"(b[0]), "r"(b[1]))

__device__ __forceinline__ void cp_async16(void* dst, const void* src) {
    uint32_t s = (uint32_t)__cvta_generic_to_shared(dst);
    asm volatile("cp.async.cg.shared.global [%0], [%1], 16;\n" :: "r"(s), "l"(src));
}
__device__ __forceinline__ void cp_commit() {
    asm volatile("cp.async.commit_group;\n");
}
template<int N> __device__ __forceinline__ void cp_wait() {
    asm volatile("cp.async.wait_group %0;\n" :: "n"(N));
}

// ---------------------------------------------------------------------------
// cvt: fp32 weights -> fp16 pair-permuted; biases -> fp32 concat copy.
// ---------------------------------------------------------------------------
#define NSEG 10
struct CvtArgs {
    const float* s[NSEG];
    void* d[NSEG];
    int end[NSEG];
    int perm;
};

__global__ void __launch_bounds__(256) cvt_all_kernel(CvtArgs a, int totalg)
{
    const int i = blockIdx.x * 256 + threadIdx.x;
    if (i >= totalg) return;
    int j = 0;
    #pragma unroll
    for (int t = 0; t < NSEG - 1; ++t)
        if (i >= a.end[t]) j = t + 1;
    const int gi = i - (j ? a.end[j - 1] : 0);
    const float4* s = (const float4*)a.s[j] + gi * 4;
    float4 f0 = s[0], f1 = s[1], f2 = s[2], f3 = s[3];
    if ((a.perm >> j) & 1) {
        float n[16] = { f0.x,f0.y,f0.z,f0.w, f1.x,f1.y,f1.z,f1.w,
                        f2.x,f2.y,f2.z,f2.w, f3.x,f3.y,f3.z,f3.w };
        uint32_t w[8];
        #pragma unroll
        for (int p = 0; p < 8; ++p) {
            const int pp = (p & 3) * 2 + (p >> 2);
            __half2 h = __floats2half2_rn(n[2 * p], n[2 * p + 1]);
            w[pp] = *(uint32_t*)&h;
        }
        uint4* d = (uint4*)a.d[j] + gi * 2;
        uint4 o0; o0.x = w[0]; o0.y = w[1]; o0.z = w[2]; o0.w = w[3];
        uint4 o1; o1.x = w[4]; o1.y = w[5]; o1.z = w[6]; o1.w = w[7];
        d[0] = o0; d[1] = o1;
    } else {
        float4* d = (float4*)a.d[j] + gi * 4;
        d[0] = f0; d[1] = f1; d[2] = f2; d[3] = f3;
    }
}

// ---------------------------------------------------------------------------
// RMSNorm: fp32 in -> half pair-permuted out.
// ---------------------------------------------------------------------------
__global__ void __launch_bounds__(128) rmsnorm_kernel(
    const float* __restrict__ x, const float* __restrict__ w,
    __half* __restrict__ o)
{
    const int row = blockIdx.x;
    const float* xr = x + (size_t)row * D_MODEL;
    const int t = threadIdx.x;
    const int c0 = 16 * t;

    float4 f0 = *(const float4*)(xr + c0);
    float4 f1 = *(const float4*)(xr + c0 + 4);
    float4 f2 = *(const float4*)(xr + c0 + 8);
    float4 f3 = *(const float4*)(xr + c0 + 12);
    float n[16] = { f0.x,f0.y,f0.z,f0.w, f1.x,f1.y,f1.z,f1.w,
                    f2.x,f2.y,f2.z,f2.w, f3.x,f3.y,f3.z,f3.w };
    float ss = 0.f;
    #pragma unroll
    for (int i = 0; i < 16; ++i) ss += n[i] * n[i];
    #pragma unroll
    for (int off = 16; off; off >>= 1)
        ss += __shfl_xor_sync(0xffffffffu, ss, off);
    __shared__ float warp_s[4];
    if ((t & 31) == 0) warp_s[t >> 5] = ss;
    __syncthreads();
    float tot = warp_s[0] + warp_s[1] + warp_s[2] + warp_s[3];
    const float inv = rsqrtf(tot * (1.0f / D_MODEL) + 1e-6f);

    float4 w0 = *(const float4*)(w + c0);
    float4 w1 = *(const float4*)(w + c0 + 4);
    float4 w2 = *(const float4*)(w + c0 + 8);
    float4 w3 = *(const float4*)(w + c0 + 12);
    float wv[16] = { w0.x,w0.y,w0.z,w0.w, w1.x,w1.y,w1.z,w1.w,
                     w2.x,w2.y,w2.z,w2.w, w3.x,w3.y,w3.z,w3.w };
    uint32_t wd[8];
    #pragma unroll
    for (int p = 0; p < 8; ++p) {
        const int pp = (p & 3) * 2 + (p >> 2);
        __half2 h = __floats2half2_rn(n[2 * p] * inv * wv[2 * p],
                                      n[2 * p + 1] * inv * wv[2 * p + 1]);
        wd[pp] = *(uint32_t*)&h;
    }
    uint4* d = (uint4*)(o + (size_t)row * D_MODEL + c0);
    uint4 o0; o0.x = wd[0]; o0.y = wd[1]; o0.z = wd[2]; o0.w = wd[3];
    uint4 o1; o1.x = wd[4]; o1.y = wd[5]; o1.z = wd[6]; o1.w = wd[7];
    d[0] = o0; d[1] = o1;
}

// ---------------------------------------------------------------------------
// FP16 GEMM (R12/1320us config): 128x128 tile, 8 warps 64x32, BK=64,
// 2-stage cp.async, LDS.64 fragments on pair-permuted operands, 2 CTAs/SM.
//   EPI 0: +bias[col]  EPI 1: +aux fp32 matrix
//   OUT 0: fp32 plain  OUT 1: half pair-perm  OUT 2: half plain
//   OUT 3: qkv special — q/k plain half to Cv, v transposed to Cv2
// ---------------------------------------------------------------------------
#define GSTW 40
#define STAGE_W (2 * 128 * GSTW)
#define GEMM_SMEM (2 * STAGE_W * 4)

template<int EPI, int OUT>
__global__ void __launch_bounds__(256, 2) gemm_f16(
    const __half* __restrict__ A, const __half* __restrict__ W,
    const void* aux, void* __restrict__ Cv, void* __restrict__ Cv2,
    int M, int N, int K)
{
    extern __shared__ uint32_t smw[];
    const int tid  = threadIdx.x;
    const int warp = tid >> 5;
    const int lane = tid & 31;
    const int bm = blockIdx.y * 128;
    const int bn = blockIdx.x * 128;
    const int m_w = (warp >> 2) * 64;
    const int n_w = (warp & 3) * 32;
    const int lr4 = lane >> 2;
    const int lk  = lane & 3;

    const __half* Ab = A + (size_t)bm * K;
    const __half* Wb = W + (size_t)bn * K;

    float acc[4][4][4];
    #pragma unroll
    for (int mt = 0; mt < 4; ++mt)
        #pragma unroll
        for (int nt = 0; nt < 4; ++nt)
            #pragma unroll
            for (int r = 0; r < 4; ++r) acc[mt][nt][r] = 0.f;

    const int nk = K / 64;

    auto load_stage = [&](int st, int k0) {
        uint32_t* Aw = smw + st * STAGE_W;
        uint32_t* Bw = Aw + 128 * GSTW;
        #pragma unroll
        for (int i = 0; i < 4; ++i) {
            const int idx = tid + i * 256;
            const int row = idx >> 3;
            const int ch  = idx & 7;
            cp_async16(&Aw[row * GSTW + ch * 4], Ab + (size_t)row * K + k0 + ch * 8);
            cp_async16(&Bw[row * GSTW + ch * 4], Wb + (size_t)row * K + k0 + ch * 8);
        }
    };

    load_stage(0, 0);   cp_commit();
    if (nk > 1) load_stage(1, 64);
    cp_commit();

    for (int kt = 0; kt < nk; ++kt) {
        cp_wait<1>();
        __syncthreads();

        const uint32_t* As = smw + (kt & 1) * STAGE_W;
        const uint32_t* Bs = As + 128 * GSTW;
        #pragma unroll
        for (int kk = 0; kk < 4; ++kk) {
            const int k0 = kk * 8;
            uint32_t afr[4][4], bfr[4][2];
            #pragma unroll
            for (int mt = 0; mt < 4; ++mt) {
                const int r = m_w + mt * 16 + lr4;
                const uint2 lo = *(const uint2*)&As[r * GSTW + k0 + 2 * lk];
                const uint2 hi = *(const uint2*)&As[(r + 8) * GSTW + k0 + 2 * lk];
                afr[mt][0] = lo.x; afr[mt][2] = lo.y;
                afr[mt][1] = hi.x; afr[mt][3] = hi.y;
            }
            #pragma unroll
            for (int nt = 0; nt < 4; ++nt) {
                const int rn = n_w + nt * 8 + lr4;
                const uint2 bb = *(const uint2*)&Bs[rn * GSTW + k0 + 2 * lk];
                bfr[nt][0] = bb.x; bfr[nt][1] = bb.y;
            }
            #pragma unroll
            for (int mt = 0; mt < 4; ++mt)
                #pragma unroll
                for (int nt = 0; nt < 4; ++nt)
                    MMA_F16(acc[mt][nt], afr[mt], bfr[nt]);
        }
        __syncthreads();
        if (kt + 2 < nk) load_stage(kt & 1, (kt + 2) * 64);
        cp_commit();
    }

    // ---- epilogue ----
    #pragma unroll
    for (int mt = 0; mt < 4; ++mt) {
        #pragma unroll
        for (int half = 0; half < 2; ++half) {
            const int row = bm + m_w + mt * 16 + lr4 + half * 8;
            const size_t base = (size_t)row * N;
            #pragma unroll
            for (int nt = 0; nt < 4; ++nt) {
                const int col = bn + n_w + nt * 8 + 2 * lk;
                float v0 = acc[mt][nt][half * 2 + 0];
                float v1 = acc[mt][nt][half * 2 + 1];
                if (EPI == 0) {
                    if (aux) {
                        const float* bz = (const float*)aux;
                        v0 += bz[col]; v1 += bz[col + 1];
                    }
                } else if (EPI == 1) {
                    const float* r = (const float*)aux;
                    v0 += r[base + col]; v1 += r[base + col + 1];
                }
                if (OUT == 0) {
                    float2 r; r.x = v0; r.y = v1;
                    *(float2*)((float*)Cv + base + col) = r;
                } else if (OUT == 1) {
                    *(__half2*)((__half*)Cv + base + ppos(col)) = __floats2half2_rn(v0, v1);
                } else if (OUT == 2) {
                    *(__half2*)((__half*)Cv + base + col) = __floats2half2_rn(v0, v1);
                } else {
                    if (col < VOFF) {
                        *(__half2*)((__half*)Cv + base + col) = __floats2half2_rn(v0, v1);
                    } else {
                        const int c = col - VOFF;
                        const int gidx = c >> 7, d = c & 127;
                        const int bb = row >> 11, sp = row & (SEQ - 1);
                        __half* vt = (__half*)Cv2 +
                            ((size_t)(bb * KVHEAD + gidx) * HDIM + d) * SEQ + sp;
                        vt[0]   = __float2half_rn(v0);
                        vt[SEQ] = __float2half_rn(v1);
                    }
                }
            }
        }
    }
}

// ---------------------------------------------------------------------------
// Fused gate+up GEMM (R12 config): BK=64, 2-stage, one A-tile, both weights,
// silu(g)*u in-register -> act (half, pair-perm).
// ---------------------------------------------------------------------------
__global__ void __launch_bounds__(256, 2) gemm_gateup(
    const __half* __restrict__ A, const __half* __restrict__ Wg,
    const __half* __restrict__ Wu, __half* __restrict__ act,
    int M, int N, int K)
{
    extern __shared__ uint32_t smw[];
    const int tid  = threadIdx.x;
    const int warp = tid >> 5;
    const int lane = tid & 31;
    const int bm = blockIdx.y * 128;
    const int bn = blockIdx.x * 64;
    const int m_w = (warp >> 2) * 64;
    const int n_w = (warp & 3) * 16;
    const int lr4 = lane >> 2;
    const int lk  = lane & 3;

    const __half* Ab = A  + (size_t)bm * K;
    const __half* Gb = Wg + (size_t)bn * K;
    const __half* Ub = Wu + (size_t)bn * K;

    float ag[4][2][4], au[4][2][4];
    #pragma unroll
    for (int mt = 0; mt < 4; ++mt)
        #pragma unroll
        for (int nt = 0; nt < 2; ++nt)
            #pragma unroll
            for (int r = 0; r < 4; ++r) { ag[mt][nt][r] = 0.f; au[mt][nt][r] = 0.f; }

    const int nk = K / 64;

    auto load_stage = [&](int st, int k0) {
        uint32_t* Aw = smw + st * STAGE_W;
        uint32_t* Gw = Aw + 128 * GSTW;
        uint32_t* Uw = Aw + 192 * GSTW;
        #pragma unroll
        for (int i = 0; i < 4; ++i) {
            const int idx = tid + i * 256;
            const int row = idx >> 3;
            const int ch  = idx & 7;
            cp_async16(&Aw[row * GSTW + ch * 4], Ab + (size_t)row * K + k0 + ch * 8);
        }
        #pragma unroll
        for (int i = 0; i < 2; ++i) {
            const int idx = tid + i * 256;
            const int row = idx >> 3;
            const int ch  = idx & 7;
            cp_async16(&Gw[row * GSTW + ch * 4], Gb + (size_t)row * K + k0 + ch * 8);
            cp_async16(&Uw[row * GSTW + ch * 4], Ub + (size_t)row * K + k0 + ch * 8);
        }
    };

    load_stage(0, 0);   cp_commit();
    if (nk > 1) load_stage(1, 64);
    cp_commit();

    for (int kt = 0; kt < nk; ++kt) {
        cp_wait<1>();
        __syncthreads();

        const uint32_t* As = smw + (kt & 1) * STAGE_W;
        const uint32_t* Gs = As + 128 * GSTW;
        const uint32_t* Us = As + 192 * GSTW;
        #pragma unroll
        for (int kk = 0; kk < 4; ++kk) {
            const int k0 = kk * 8;
            uint32_t afr[4][4], gfr[2][2], ufr[2][2];
            #pragma unroll
            for (int mt = 0; mt < 4; ++mt) {
                const int r = m_w + mt * 16 + lr4;
                const uint2 lo = *(const uint2*)&As[r * GSTW + k0 + 2 * lk];
                const uint2 hi = *(const uint2*)&As[(r + 8) * GSTW + k0 + 2 * lk];
                afr[mt][0] = lo.x; afr[mt][2] = lo.y;
                afr[mt][1] = hi.x; afr[mt][3] = hi.y;
            }
            #pragma unroll
            for (int nt = 0; nt < 2; ++nt) {
                const int rn = n_w + nt * 8 + lr4;
                const uint2 gg = *(const uint2*)&Gs[rn * GSTW + k0 + 2 * lk];
                gfr[nt][0] = gg.x; gfr[nt][1] = gg.y;
                const uint2 uu = *(const uint2*)&Us[rn * GSTW + k0 + 2 * lk];
                ufr[nt][0] = uu.x; ufr[nt][1] = uu.y;
            }
            #pragma unroll
            for (int mt = 0; mt < 4; ++mt)
                #pragma unroll
                for (int nt = 0; nt < 2; ++nt) {
                    MMA_F16(ag[mt][nt], afr[mt], gfr[nt]);
                    MMA_F16(au[mt][nt], afr[mt], ufr[nt]);
                }
        }
        __syncthreads();
        if (kt + 2 < nk) load_stage(kt & 1, (kt + 2) * 64);
        cp_commit();
    }

    // ---- epilogue: act = silu(g) * u, half pair-perm ----
    #pragma unroll
    for (int mt = 0; mt < 4; ++mt) {
        #pragma unroll
        for (int half = 0; half < 2; ++half) {
            const int row = bm + m_w + mt * 16 + lr4 + half * 8;
            const size_t base = (size_t)row * N;
            #pragma unroll
            for (int nt = 0; nt < 2; ++nt) {
                const int col = bn + n_w + nt * 8 + 2 * lk;
                const float ga = ag[mt][nt][half * 2 + 0];
                const float gb = ag[mt][nt][half * 2 + 1];
                const float v0 = au[mt][nt][half * 2 + 0] * ga / (1.0f + __expf(-ga));
                const float v1 = au[mt][nt][half * 2 + 1] * gb / (1.0f + __expf(-gb));
                *(__half2*)(act + base + ppos(col)) = __floats2half2_rn(v0, v1);
            }
        }
    }
}

// ---------------------------------------------------------------------------
// Flash attention (R13, measured 158us): fp16 MMA, FKT=128 (mask only on
// final diagonal tile), P in registers, V pre-transposed.
// ---------------------------------------------------------------------------
#define FQT 128
#define FKT 128
#define KSTH 136                       // halves (68 words/row, === 4 mod 32)
#define VSTH 136
#define KV_STAGE_H (FKT * KSTH + HDIM * VSTH)            // 34816 halves
#define FLASH_SMEM (2 * KV_STAGE_H * 2)                  // 139264 bytes

__global__ void __launch_bounds__(256) flash_tc_kernel(
    const __half* __restrict__ qkv, const __half* __restrict__ vT,
    __half* __restrict__ Ob)
{
    extern __shared__ __half fsh[];
    __half* S0 = fsh;
    __half* S1 = fsh + KV_STAGE_H;

    const int bx   = (SEQ / FQT - 1) - blockIdx.x;   // heavy tiles first
    const int hh   = blockIdx.y;
    const int b    = blockIdx.z;
    const int g    = hh & (KVHEAD - 1);
    const int tid  = threadIdx.x;
    const int warp = tid >> 5;
    const int lane = tid & 31;
    const int lr   = lane >> 2;
    const int lq   = lane & 3;
    const int mb   = warp * 16;
    const int qbase = bx * FQT;
    const float scale = 0.08838834764831845f;

    // ---- stage Q into S0, extract fp16 fragments ----
    const __half* qp = qkv + ((size_t)(b * SEQ + qbase)) * QKV_N + hh * HDIM;
    #pragma unroll
    for (int it = 0; it < 8; ++it) {
        const int idx = tid + it * 256;
        const int row = idx >> 4;
        const int ch  = idx & 15;
        *(uint4*)&S0[row * KSTH + ch * 8] =
            *(const uint4*)(qp + (size_t)row * QKV_N + ch * 8);
    }
    __syncthreads();
    uint32_t qf[8][4];
    #pragma unroll
    for (int kk = 0; kk < 8; ++kk) {
        const int k0 = kk * 16 + 2 * lq;
        qf[kk][0] = *(const uint32_t*)&S0[(mb + lr)     * KSTH + k0];
        qf[kk][1] = *(const uint32_t*)&S0[(mb + lr + 8) * KSTH + k0];
        qf[kk][2] = *(const uint32_t*)&S0[(mb + lr)     * KSTH + k0 + 8];
        qf[kk][3] = *(const uint32_t*)&S0[(mb + lr + 8) * KSTH + k0 + 8];
    }
    __syncthreads();

    const int nkt = bx + 1;

    auto load_kv = [&](__half* St, int ktb) {
        __half* Kd = St;
        __half* Vd = St + FKT * KSTH;
        const __half* kp = qkv + ((size_t)(b * SEQ + ktb)) * QKV_N + D_MODEL + g * HDIM;
        const __half* vp = vT + ((size_t)(b * KVHEAD + g) * HDIM) * SEQ + ktb;
        #pragma unroll
        for (int it = 0; it < 8; ++it) {
            const int idx = tid + it * 256;
            const int row = idx >> 4, ch = idx & 15;
            cp_async16(&Kd[row * KSTH + ch * 8], kp + (size_t)row * QKV_N + ch * 8);
            cp_async16(&Vd[row * VSTH + ch * 8], vp + (size_t)row * SEQ + ch * 8);
        }
    };

    load_kv(S0, 0);
    cp_commit();
    if (nkt > 1) load_kv(S1, FKT);
    cp_commit();

    float o[16][4];
    #pragma unroll
    for (int nt = 0; nt < 16; ++nt)
        o[nt][0] = o[nt][1] = o[nt][2] = o[nt][3] = 0.f;
    float m0 = -1e30f, m1 = -1e30f, l0 = 0.f, l1 = 0.f;
    const int r0g = qbase + mb + lr;
    const int r1g = r0g + 8;

    for (int kt = 0; kt < nkt; ++kt) {
        cp_wait<1>();
        __syncthreads();
        const __half* St = (kt & 1) ? S1 : S0;
        const __half* Ks = St;
        const __half* Vs = St + FKT * KSTH;
        const int ktb = kt * FKT;

        // ---- S = Q K^T (16 x 128 per warp), fp16 MMA ----
        float s[16][4];
        #pragma unroll
        for (int nt = 0; nt < 16; ++nt)
            s[nt][0] = s[nt][1] = s[nt][2] = s[nt][3] = 0.f;
        #pragma unroll
        for (int kk = 0; kk < 8; ++kk) {
            const int k0 = kk * 16 + 2 * lq;
            #pragma unroll
            for (int nt = 0; nt < 16; ++nt) {
                uint32_t bfr[2];
                bfr[0] = *(const uint32_t*)&Ks[(nt * 8 + lr) * KSTH + k0];
                bfr[1] = *(const uint32_t*)&Ks[(nt * 8 + lr) * KSTH + k0 + 8];
                MMA_F16(s[nt], qf[kk], bfr);
            }
        }

        // ---- scale (+ causal mask on last tile only) + max ----
        float mx0 = -1e30f, mx1 = -1e30f;
        if (kt == nkt - 1) {
            #pragma unroll
            for (int nt = 0; nt < 16; ++nt) {
                const int c = ktb + nt * 8 + 2 * lq;
                s[nt][0] = (c     <= r0g) ? s[nt][0] * scale : -1e30f;
                s[nt][1] = (c + 1 <= r0g) ? s[nt][1] * scale : -1e30f;
                s[nt][2] = (c     <= r1g) ? s[nt][2] * scale : -1e30f;
                s[nt][3] = (c + 1 <= r1g) ? s[nt][3] * scale : -1e30f;
                mx0 = fmaxf(mx0, fmaxf(s[nt][0], s[nt][1]));
                mx1 = fmaxf(mx1, fmaxf(s[nt][2], s[nt][3]));
            }
        } else {
            #pragma unroll
            for (int nt = 0; nt < 16; ++nt) {
                s[nt][0] *= scale; s[nt][1] *= scale;
                s[nt][2] *= scale; s[nt][3] *= scale;
                mx0 = fmaxf(mx0, fmaxf(s[nt][0], s[nt][1]));
                mx1 = fmaxf(mx1, fmaxf(s[nt][2], s[nt][3]));
            }
        }
        mx0 = fmaxf(mx0, __shfl_xor_sync(0xffffffffu, mx0, 1));
        mx0 = fmaxf(mx0, __shfl_xor_sync(0xffffffffu, mx0, 2));
        mx1 = fmaxf(mx1, __shfl_xor_sync(0xffffffffu, mx1, 1));
        mx1 = fmaxf(mx1, __shfl_xor_sync(0xffffffffu, mx1, 2));
        const float mn0 = fmaxf(m0, mx0), mn1 = fmaxf(m1, mx1);
        const float al0 = __expf(m0 - mn0), al1 = __expf(m1 - mn1);
        m0 = mn0; m1 = mn1;

        // ---- exp -> P as half2 A-fragments in registers ----
        uint32_t ph[16][2];
        float ps0 = 0.f, ps1 = 0.f;
        #pragma unroll
        for (int nt = 0; nt < 16; ++nt) {
            const float p0 = __expf(s[nt][0] - mn0);
            const float p1 = __expf(s[nt][1] - mn0);
            const float p2 = __expf(s[nt][2] - mn1);
            const float p3 = __expf(s[nt][3] - mn1);
            ps0 += p0 + p1; ps1 += p2 + p3;
            __half2 h0 = __floats2half2_rn(p0, p1);
            __half2 h1 = __floats2half2_rn(p2, p3);
            ph[nt][0] = *(uint32_t*)&h0;
            ph[nt][1] = *(uint32_t*)&h1;
        }
        ps0 += __shfl_xor_sync(0xffffffffu, ps0, 1);
        ps0 += __shfl_xor_sync(0xffffffffu, ps0, 2);
        ps1 += __shfl_xor_sync(0xffffffffu, ps1, 1);
        ps1 += __shfl_xor_sync(0xffffffffu, ps1, 2);
        l0 = l0 * al0 + ps0;
        l1 = l1 * al1 + ps1;

        #pragma unroll
        for (int nt = 0; nt < 16; ++nt) {
            o[nt][0] *= al0; o[nt][1] *= al0;
            o[nt][2] *= al1; o[nt][3] *= al1;
        }

        // ---- O += P V (K=128 -> 8 k16 chunks), P from registers ----
        #pragma unroll
        for (int kk = 0; kk < 8; ++kk) {
            const int k0 = kk * 16 + 2 * lq;
            uint32_t a[4];
            a[0] = ph[2 * kk][0];
            a[1] = ph[2 * kk][1];
            a[2] = ph[2 * kk + 1][0];
            a[3] = ph[2 * kk + 1][1];
            #pragma unroll
            for (int nt = 0; nt < 16; ++nt) {
                uint32_t bfr[2];
                bfr[0] = *(const uint32_t*)&Vs[(nt * 8 + lr) * VSTH + k0];
                bfr[1] = *(const uint32_t*)&Vs[(nt * 8 + lr) * VSTH + k0 + 8];
                MMA_F16(o[nt], a, bfr);
            }
        }
        __syncthreads();

        const int nx = kt + 2;
        if (nx < nkt) load_kv((nx & 1) ? S1 : S0, nx * FKT);
        cp_commit();
    }

    // write O: half pair-perm (feeds o-proj GEMM)
    const float i0 = 1.0f / l0, i1 = 1.0f / l1;
    __half* op = Ob + ((size_t)(b * SEQ + qbase + mb)) * D_MODEL;
    #pragma unroll
    for (int nt = 0; nt < 16; ++nt) {
        const int label = hh * HDIM + nt * 8 + 2 * lq;
        const int pos = ppos(label);
        *(__half2*)(op + (size_t)lr * D_MODEL + pos) =
            __floats2half2_rn(o[nt][0] * i0, o[nt][1] * i0);
        *(__half2*)(op + (size_t)(lr + 8) * D_MODEL + pos) =
            __floats2half2_rn(o[nt][2] * i1, o[nt][3] * i1);
    }
}

// ---------------------------------------------------------------------------
// Launch sequence
// ---------------------------------------------------------------------------
extern "C" void kernel_launch(void* const* d_in, const int* in_sizes, int n_in,
                              void* d_out, int out_size)
{
    const float* x      = (const float*)d_in[0];
    const float* ln1_w  = (const float*)d_in[1];
    const float* q_w    = (const float*)d_in[2];
    const float* q_b    = (const float*)d_in[3];
    const float* k_w    = (const float*)d_in[4];
    const float* k_b    = (const float*)d_in[5];
    const float* v_w    = (const float*)d_in[6];
    const float* v_b    = (const float*)d_in[7];
    const float* o_w    = (const float*)d_in[8];
    const float* ln2_w  = (const float*)d_in[9];
    const float* gate_w = (const float*)d_in[10];
    const float* up_w   = (const float*)d_in[11];
    const float* down_w = (const float*)d_in[12];
    float* out = (float*)d_out;

    __half *h, *h2, *act, *qkv, *vT;
    float *bq;
    __half *wqkv, *wo, *wg, *wu, *wd;
    cudaGetSymbolAddress((void**)&h,    g_h);
    cudaGetSymbolAddress((void**)&h2,   g_h2);
    cudaGetSymbolAddress((void**)&qkv,  g_qkv);
    cudaGetSymbolAddress((void**)&vT,   g_vT);
    cudaGetSymbolAddress((void**)&act,  g_act);
    cudaGetSymbolAddress((void**)&wqkv, w_qkvh);
    cudaGetSymbolAddress((void**)&wo,   w_oh);
    cudaGetSymbolAddress((void**)&wg,   w_gh);
    cudaGetSymbolAddress((void**)&wu,   w_uh);
    cudaGetSymbolAddress((void**)&wd,   w_dh);
    cudaGetSymbolAddress((void**)&bq,   b_qkv);

    cudaFuncSetAttribute(gemm_f16<0,3>, cudaFuncAttributeMaxDynamicSharedMemorySize, GEMM_SMEM);
    cudaFuncSetAttribute(gemm_f16<1,0>, cudaFuncAttributeMaxDynamicSharedMemorySize, GEMM_SMEM);
    cudaFuncSetAttribute(gemm_gateup,   cudaFuncAttributeMaxDynamicSharedMemorySize, GEMM_SMEM);
    cudaFuncSetAttribute(flash_tc_kernel, cudaFuncAttributeMaxDynamicSharedMemorySize, FLASH_SMEM);

    // 0. convert weights (pair-perm fp16) + concat biases
    {
        CvtArgs a;
        const float* srcs[NSEG] = { q_w, k_w, v_w, o_w, gate_w, up_w, down_w,
                                    q_b, k_b, v_b };
        void* dsts[NSEG] = { (void*)wqkv,
                             (void*)(wqkv + (size_t)D_MODEL * D_MODEL),
                             (void*)(wqkv + (size_t)VOFF * D_MODEL),
                             (void*)wo, (void*)wg, (void*)wu, (void*)wd,
                             (void*)bq, (void*)(bq + D_MODEL), (void*)(bq + VOFF) };
        const long long n[NSEG] = {
            (long long)D_MODEL*D_MODEL, (long long)KD*D_MODEL, (long long)KD*D_MODEL,
            (long long)D_MODEL*D_MODEL, (long long)FF*D_MODEL, (long long)FF*D_MODEL,
            (long long)D_MODEL*FF, D_MODEL, KD, KD };
        int accg = 0;
        for (int i = 0; i < NSEG; ++i) {
            a.s[i] = srcs[i]; a.d[i] = dsts[i];
            accg += (int)(n[i] / 16); a.end[i] = accg;
        }
        a.perm = 0x7F;
        cvt_all_kernel<<<(accg + 255) / 256, 256>>>(a, accg);
    }

    // 1. h = rmsnorm(x, ln1)  [half, perm]
    rmsnorm_kernel<<<MTOT, 128>>>(x, ln1_w, h);

    // 2. fused qkv projection: q/k plain half, v transposed
    gemm_f16<0,3><<<dim3(QKV_N/128, MTOT/128), 256, GEMM_SMEM>>>(
        h, wqkv, bq, qkv, vT, MTOT, QKV_N, D_MODEL);

    // 3. flash attention (fp16, FKT=128) -> g_h
    flash_tc_kernel<<<dim3(SEQ/FQT, NHEAD, BATCH), 256, FLASH_SMEM>>>(qkv, vT, h);

    // 4. x1 = x + attn @ o_w^T -> d_out
    gemm_f16<1,0><<<dim3(D_MODEL/128, MTOT/128), 256, GEMM_SMEM>>>(
        h, wo, x, out, nullptr, MTOT, D_MODEL, D_MODEL);

    // 5. h2 = rmsnorm(x1, ln2)  [half, perm]
    rmsnorm_kernel<<<MTOT, 128>>>(out, ln2_w, h2);

    // 6. act = silu(h2 @ gate_w^T) * (h2 @ up_w^T)  [fused]
    gemm_gateup<<<dim3(FF/64, MTOT/128), 256, GEMM_SMEM>>>(
        h2, wg, wu, act, MTOT, FF, D_MODEL);

    // 7. out = x1 + act @ down_w^T -> d_out
    gemm_f16<1,0><<<dim3(D_MODEL/128, MTOT/128), 256, GEMM_SMEM>>>(
        act, wd, out, out, nullptr, MTOT, D_MODEL, FF);
}